// round 12
// baseline (speedup 1.0000x reference)
#include <cuda_runtime.h>
#include <cstdint>

// IOVPreTrainedEmbeddings: out[b,s,:] = (oov_map[x[b,s]] >= 0)
//                                         ? oov_embed[oov_map[x[b,s]], :]
//                                         : w2v[x[b,s], :]
//
// x [131072] i32, w2v [100000,300] f32, oov_embed [5000,300] f32,
// oov_map [100000] i32, out [131072,300] f32.
//
// R11: persistent single-wave grid. R5-R10 established the per-launch
// memory work is at the ~5.5TB/s mixed-traffic floor (~42us kernel) and
// L2 policy tweaks are noise. Remaining overhead: 4800 CTAs = 4 waves
// (occ 8 CTAs/SM -> n_conc 1184), i.e. ~3 wave transitions (~2360cyc each)
// + per-wave lift. Launch exactly one wave (1184 CTAs); each CTA loops
// over 2048-float4 chunks. Memory body identical to the R7 champion:
// evict_last-pinned nc loads + __stcs streaming stores, 32 regs.

static constexpr int TOKENS = 128 * 1024;     // B*S
static constexpr int DIM    = 300;
static constexpr int VEC    = DIM / 4;        // 75 float4 per row (1200B stride)
static constexpr long long TOTAL4 = (long long)TOKENS * VEC;  // 9,830,400

static constexpr int THREADS = 256;
static constexpr int UNROLL  = 8;
static constexpr int CHUNK   = THREADS * UNROLL;                 // 2048 f4 per chunk
static constexpr int NCHUNKS = (int)(TOTAL4 / CHUNK);            // 4800, exact
static constexpr int GRID    = 1184;                             // 8 CTAs/SM x 148 SMs = 1 wave

__device__ __forceinline__ uint64_t policy_evict_last() {
    uint64_t pol;
    asm("createpolicy.fractional.L2::evict_last.b64 %0, 1.0;" : "=l"(pol));
    return pol;
}

__device__ __forceinline__ int ldg_i32_el(const int* p, uint64_t pol) {
    int v;
    asm volatile("ld.global.nc.L2::cache_hint.b32 %0, [%1], %2;"
                 : "=r"(v) : "l"(p), "l"(pol));
    return v;
}

__device__ __forceinline__ float4 ldg_f4_el(const float4* p, uint64_t pol) {
    float4 v;
    asm volatile("ld.global.nc.L2::cache_hint.v4.f32 {%0,%1,%2,%3}, [%4], %5;"
                 : "=f"(v.x), "=f"(v.y), "=f"(v.z), "=f"(v.w)
                 : "l"(p), "l"(pol));
    return v;
}

__global__ __launch_bounds__(THREADS)
void iov_gather_pers_kernel(const int*    __restrict__ x,
                            const float4* __restrict__ w2v,       // row stride VEC
                            const float4* __restrict__ oov_embed, // row stride VEC
                            const int*    __restrict__ oov_map,
                            float4*       __restrict__ out)
{
    const uint64_t pol = policy_evict_last();
    const int tid = threadIdx.x;

    // Persistent loop: one wave of CTAs, each takes chunks in grid-stride.
    for (int c = blockIdx.x; c < NCHUNKS; c += GRID) {
        const int base = c * CHUNK + tid;   // f4 index of this thread's k=0 lane

        int id[UNROLL];
        int row[UNROLL];

        // Phase 1: token ids (L1/L2-resident broadcast).
        #pragma unroll
        for (int k = 0; k < UNROLL; k++) {
            int token = (base + k * THREADS) / VEC;   // mul-shift div by 75
            id[k] = ldg_i32_el(&x[token], pol);
        }

        // Phase 2: oov_map gathers (400KB table, pinned).
        #pragma unroll
        for (int k = 0; k < UNROLL; k++)
            row[k] = ldg_i32_el(&oov_map[id[k]], pol);

        // Phase 3+4: payload gather (evict_last keeps tables L2-resident
        // across graph replays) + evict-first streaming store.
        #pragma unroll
        for (int k = 0; k < UNROLL; k++) {
            int i     = base + k * THREADS;
            int token = i / VEC;
            int chunk = i - token * VEC;
            const float4* src = (row[k] >= 0)
                ? (oov_embed + (long long)row[k] * VEC + chunk)
                : (w2v       + (long long)id[k]  * VEC + chunk);
            float4 v = ldg_f4_el(src, pol);
            __stcs(&out[i], v);
        }
    }
}

extern "C" void kernel_launch(void* const* d_in, const int* in_sizes, int n_in,
                              void* d_out, int out_size)
{
    const int*    x         = (const int*)   d_in[0];
    const float4* w2v       = (const float4*)d_in[1];
    const float4* oov_embed = (const float4*)d_in[2];
    const int*    oov_map   = (const int*)   d_in[3];
    float4*       out       = (float4*)d_out;

    iov_gather_pers_kernel<<<GRID, THREADS>>>(x, w2v, oov_embed, oov_map, out);
}